// round 4
// baseline (speedup 1.0000x reference)
#include <cuda_runtime.h>

// ============================================================================
// SparseSubdivideBlock3d: conv1(27-tap) -> SiLU -> subdivide(x8) -> conv2 -> SiLU
//
// Key identity: child i = 8v+p (p in {0,1}^3). Fine neighbor at offset `off`
// has parent v + d, d = floor((p+off)/2) in {-1,0,1}^3, and validity/activity
// of the fine neighbor == validity/activity of coarse cell v+d. Hence
//   nbr2[8v+p, k] >> 3 == nbr1[v, col27(d)]   (pad 8N -> N)
// and since repeat(h,8)[j] = h[j>>3], layer 2 becomes an 8-tap conv on the
// COARSE grid with pre-combined weights Wc[p][e] = sum of W2[k] over all k
// mapping to the same parent offset d = e + p - 1 (per-dim, e in {0,1}^3).
//
// (R3 = R1 resubmitted verbatim again: rounds 2 and 3 both died in broker
//  infra before compiling/running the kernel.)
// ============================================================================

#define N_VOX 40000
#define CI 128
#define CO 128
#define BM 64
#define BK 32
#define BN 128

__device__ float g_h[(size_t)(N_VOX + 1) * CI];        // layer-1 output + zero pad row
__device__ float g_wc[8 * 8 * CI * CO];                // combined layer-2 weights [p][e][ci][co]

__device__ __forceinline__ float silu_f(float x) {
    return x / (1.0f + __expf(-x));
}

// ---------------------------------------------------------------------------
// Build Wc[p][e] = sum over fine offsets `off` with floor((p+off)/2) = e+p-1
// (per-dim) of W2[k(off)]. Also zero the pad row of g_h.
// grid = 64 blocks (one per (p,e)), 256 threads.
// ---------------------------------------------------------------------------
__global__ void build_wc_kernel(const float* __restrict__ W2) {
    const int pe = blockIdx.x;            // 0..63
    const int p = pe >> 3, e = pe & 7;
    const int pp[3] = { (p >> 2) & 1, (p >> 1) & 1, p & 1 };
    const int ee[3] = { (e >> 2) & 1, (e >> 1) & 1, e & 1 };

    // Per-dimension set of fine offsets contributing to this parent offset:
    //   p=0: e=0 -> {-1}   ; e=1 -> {0, 1}
    //   p=1: e=0 -> {-1, 0}; e=1 -> {1}
    int offs[3][2], cnt[3];
    #pragma unroll
    for (int d = 0; d < 3; d++) {
        if (ee[d] == pp[d]) { cnt[d] = 1; offs[d][0] = pp[d] ? 1 : -1; offs[d][1] = 0; }
        else if (pp[d] == 0) { cnt[d] = 2; offs[d][0] = 0;  offs[d][1] = 1; }
        else                 { cnt[d] = 2; offs[d][0] = -1; offs[d][1] = 0; }
    }

    float* dst = g_wc + (size_t)pe * (CI * CO);
    for (int idx = threadIdx.x; idx < CI * CO; idx += blockDim.x) {
        float s = 0.0f;
        for (int a = 0; a < cnt[0]; a++)
            for (int b = 0; b < cnt[1]; b++)
                for (int c = 0; c < cnt[2]; c++) {
                    int k = (offs[0][a] + 1) * 9 + (offs[1][b] + 1) * 3 + (offs[2][c] + 1);
                    s += W2[(size_t)k * (CI * CO) + idx];
                }
        dst[idx] = s;
    }

    if (pe == 0) {
        for (int i = threadIdx.x; i < CI; i += blockDim.x)
            g_h[(size_t)N_VOX * CI + i] = 0.0f;
    }
}

// ---------------------------------------------------------------------------
// Implicit-GEMM sparse conv + bias + SiLU.
//   L2=false: 27 taps, W = W1, fin = feats, out row = i       (writes g_h)
//   L2=true :  8 taps, W = Wc (64 slices, indexed [p*8+e]), fin = g_h,
//              out row = 8*i+p (writes d_out)
// BM=64 voxels x BN=128 outputs per block, BK=32, 256 threads, 8x4 per thread.
// ---------------------------------------------------------------------------
template <int NOFF, bool L2>
__global__ __launch_bounds__(256)
void conv_kernel(const float* __restrict__ fin,
                 const int*   __restrict__ nbr,
                 const float* __restrict__ W,
                 const float* __restrict__ bias,
                 float*       __restrict__ out) {
    __shared__ __align__(16) float As[BK][BM];   // transposed gathered features
    __shared__ __align__(16) float Bs[BK][BN];   // weight slice
    __shared__ int sIdx[BM];

    const int tx = threadIdx.x;
    const int m0 = blockIdx.x * BM;
    const int p  = L2 ? blockIdx.y : 0;
    const int p0 = (p >> 2) & 1, p1 = (p >> 1) & 1, p2 = p & 1;

    const int ty = tx >> 5;            // 0..7  row group (warp id)
    const int tc = tx & 31;            // 0..31 col group
    const int arow = tx >> 2;          // 0..63 A-load row
    const int aq   = tx & 3;           // A-load col quad (8 floats)
    const int brow = tx >> 3;          // 0..31 B-load row
    const int bq   = tx & 7;           // B-load col group (16 floats)

    float acc[8][4];
    #pragma unroll
    for (int i = 0; i < 8; i++)
        #pragma unroll
        for (int j = 0; j < 4; j++) acc[i][j] = 0.0f;

    #pragma unroll 1
    for (int off = 0; off < NOFF; ++off) {
        int col;
        if (L2) {
            // parent offset d = e + p - 1 per dim; 27-index = (d0+1)*9+(d1+1)*3+(d2+1)
            col = (((off >> 2) & 1) + p0) * 9 + (((off >> 1) & 1) + p1) * 3 + ((off & 1) + p2);
        } else {
            col = off;
        }
        if (tx < BM) sIdx[tx] = nbr[(size_t)(m0 + tx) * 27 + col];
        __syncthreads();

        const int g = sIdx[arow];
        const float* arow_ptr = (g >= N_VOX) ? nullptr : (fin + (size_t)g * CI);
        // Layer-2 weight slice is indexed by (p, e) = p*8 + off.
        const int wslice = L2 ? (p * 8 + off) : off;
        const float* Wk = W + (size_t)wslice * (CI * CO);

        #pragma unroll 1
        for (int kt = 0; kt < CI / BK; ++kt) {
            // ---- load A tile (gather + transpose) ----
            float4 a0, a1;
            if (arow_ptr) {
                a0 = *(const float4*)(arow_ptr + kt * BK + aq * 8);
                a1 = *(const float4*)(arow_ptr + kt * BK + aq * 8 + 4);
            } else {
                a0 = make_float4(0.f, 0.f, 0.f, 0.f);
                a1 = a0;
            }
            As[aq * 8 + 0][arow] = a0.x; As[aq * 8 + 1][arow] = a0.y;
            As[aq * 8 + 2][arow] = a0.z; As[aq * 8 + 3][arow] = a0.w;
            As[aq * 8 + 4][arow] = a1.x; As[aq * 8 + 5][arow] = a1.y;
            As[aq * 8 + 6][arow] = a1.z; As[aq * 8 + 7][arow] = a1.w;

            // ---- load B tile ----
            const float* wrow = Wk + (size_t)(kt * BK + brow) * CO + bq * 16;
            *(float4*)&Bs[brow][bq * 16 + 0]  = *(const float4*)(wrow + 0);
            *(float4*)&Bs[brow][bq * 16 + 4]  = *(const float4*)(wrow + 4);
            *(float4*)&Bs[brow][bq * 16 + 8]  = *(const float4*)(wrow + 8);
            *(float4*)&Bs[brow][bq * 16 + 12] = *(const float4*)(wrow + 12);
            __syncthreads();

            // ---- compute ----
            #pragma unroll
            for (int kk = 0; kk < BK; ++kk) {
                const float4 av0 = *(const float4*)(&As[kk][ty * 8]);
                const float4 av1 = *(const float4*)(&As[kk][ty * 8 + 4]);
                const float4 bv  = *(const float4*)(&Bs[kk][tc * 4]);
                const float ar[8] = { av0.x, av0.y, av0.z, av0.w,
                                      av1.x, av1.y, av1.z, av1.w };
                const float br[4] = { bv.x, bv.y, bv.z, bv.w };
                #pragma unroll
                for (int i = 0; i < 8; i++)
                    #pragma unroll
                    for (int j = 0; j < 4; j++)
                        acc[i][j] = fmaf(ar[i], br[j], acc[i][j]);
            }
            __syncthreads();
        }
    }

    // ---- epilogue: bias + SiLU ----
    const float4 bb = *(const float4*)(bias + tc * 4);
    #pragma unroll
    for (int i = 0; i < 8; i++) {
        const int row = m0 + ty * 8 + i;
        float x0 = silu_f(acc[i][0] + bb.x);
        float x1 = silu_f(acc[i][1] + bb.y);
        float x2 = silu_f(acc[i][2] + bb.z);
        float x3 = silu_f(acc[i][3] + bb.w);
        const size_t orow = L2 ? ((size_t)row * 8 + p) : (size_t)row;
        *(float4*)(out + orow * CO + tc * 4) = make_float4(x0, x1, x2, x3);
    }
}

// ---------------------------------------------------------------------------
// Inputs (metadata order): feats, W1, b1, W2, b2, nbr1, nbr2(unused)
// Output: 320000 x 128 fp32
// ---------------------------------------------------------------------------
extern "C" void kernel_launch(void* const* d_in, const int* in_sizes, int n_in,
                              void* d_out, int out_size) {
    const float* feats = (const float*)d_in[0];
    const float* W1    = (const float*)d_in[1];
    const float* b1    = (const float*)d_in[2];
    const float* W2    = (const float*)d_in[3];
    const float* b2    = (const float*)d_in[4];
    const int*   nbr1  = (const int*)  d_in[5];
    float*       out   = (float*)d_out;

    float* hbuf = nullptr;
    float* wc   = nullptr;
    cudaGetSymbolAddress((void**)&hbuf, g_h);
    cudaGetSymbolAddress((void**)&wc, g_wc);

    // 1) combined layer-2 weights + zero pad row of h
    build_wc_kernel<<<64, 256>>>(W2);
    // 2) layer 1: 27-tap conv on 40000 voxels -> g_h
    conv_kernel<27, false><<<dim3(N_VOX / BM, 1), 256>>>(feats, nbr1, W1, b1, hbuf);
    // 3) layer 2 (collapsed): 8-tap conv on coarse grid, one launch per child corner via grid.y
    conv_kernel<8, true><<<dim3(N_VOX / BM, 8), 256>>>(hbuf, nbr1, wc, b2, out);
}

// round 6
// speedup vs baseline: 2.1894x; 2.1894x over previous
#include <cuda_runtime.h>
#include <cuda_bf16.h>
#include <cstdint>

// ============================================================================
// SparseSubdivideBlock3d via legacy HMMA (mma.sync bf16) + bf16x3 fp32 emulation.
// (tcgen05 is unavailable: harness compiles for plain sm_100, where ptxas
//  rejects tcgen05.* — confirmed R5. mma.sync.m16n8k16 bf16 assembles fine.)
//
// Algorithm (validated R4 @ fp32, rel_err 7e-7):
//   conv1: 27-tap submanifold conv, C=128->128, +bias, SiLU
//   subdivide collapse: conv2 == 8-tap conv on the COARSE grid with
//     pre-combined weights Wc[p][e] = sum W2[k], out row = 8*v + p.
// Numerics: x = hi + lo (bf16 each); A.B ~= Ahi.Bhi + Ahi.Blo + Alo.Bhi,
// fp32 accumulate; dropped Alo.Blo term ~2^-16 relative.
// ============================================================================

#define N_VOX 40000
#define C 128
#define NBLK ((N_VOX + 127) / 128)   // 313

// ---- device scratch ----
__device__ float g_wc[64 * C * C];                                // fp32 combined L2 weights [pe][ci][co]
__device__ __align__(16) __nv_bfloat16 g_w1t_hi[27 * C * C];      // W1^T [k][co][ci]
__device__ __align__(16) __nv_bfloat16 g_w1t_lo[27 * C * C];
__device__ __align__(16) __nv_bfloat16 g_wct_hi[64 * C * C];      // Wc^T [pe][co][ci]
__device__ __align__(16) __nv_bfloat16 g_wct_lo[64 * C * C];
__device__ __align__(16) __nv_bfloat16 g_f_hi[(N_VOX + 1) * C];   // feats split + zero pad row
__device__ __align__(16) __nv_bfloat16 g_f_lo[(N_VOX + 1) * C];
__device__ __align__(16) __nv_bfloat16 g_h_hi[(N_VOX + 1) * C];   // layer-1 out split + pad
__device__ __align__(16) __nv_bfloat16 g_h_lo[(N_VOX + 1) * C];

__device__ __forceinline__ float silu_f(float x) { return x / (1.0f + __expf(-x)); }

__device__ __forceinline__ uint32_t smem_u32(const void* p) {
    uint32_t a;
    asm("{ .reg .u64 t; cvta.to.shared.u64 t, %1; cvt.u32.u64 %0, t; }" : "=r"(a) : "l"(p));
    return a;
}
#define CP16(dst, src) asm volatile("cp.async.cg.shared.global [%0], [%1], 16;" :: "r"(dst), "l"(src))
#define CP_COMMIT()    asm volatile("cp.async.commit_group;" ::: "memory")
#define CP_WAIT0()     asm volatile("cp.async.wait_group 0;" ::: "memory")
#define CP_WAIT1()     asm volatile("cp.async.wait_group 1;" ::: "memory")

__device__ __forceinline__ void ldsm_x4(uint32_t* r, uint32_t a) {
    asm volatile("ldmatrix.sync.aligned.m8n8.x4.shared.b16 {%0,%1,%2,%3}, [%4];"
                 : "=r"(r[0]), "=r"(r[1]), "=r"(r[2]), "=r"(r[3]) : "r"(a));
}
__device__ __forceinline__ void mma16816(float* d, const uint32_t* a, const uint32_t* b) {
    asm volatile("mma.sync.aligned.m16n8k16.row.col.f32.bf16.bf16.f32 "
                 "{%0,%1,%2,%3}, {%4,%5,%6,%7}, {%8,%9}, {%0,%1,%2,%3};"
                 : "+f"(d[0]), "+f"(d[1]), "+f"(d[2]), "+f"(d[3])
                 : "r"(a[0]), "r"(a[1]), "r"(a[2]), "r"(a[3]), "r"(b[0]), "r"(b[1]));
}

// ---------------------------------------------------------------------------
// Prep kernels
// ---------------------------------------------------------------------------
__global__ void build_wc_kernel(const float* __restrict__ W2) {
    const int pe = blockIdx.x;                     // 0..63
    const int p = pe >> 3, e = pe & 7;
    const int pp[3] = { (p >> 2) & 1, (p >> 1) & 1, p & 1 };
    const int ee[3] = { (e >> 2) & 1, (e >> 1) & 1, e & 1 };
    int offs[3][2], cnt[3];
    #pragma unroll
    for (int d = 0; d < 3; d++) {
        if (ee[d] == pp[d]) { cnt[d] = 1; offs[d][0] = pp[d] ? 1 : -1; offs[d][1] = 0; }
        else if (pp[d] == 0) { cnt[d] = 2; offs[d][0] = 0;  offs[d][1] = 1; }
        else                 { cnt[d] = 2; offs[d][0] = -1; offs[d][1] = 0; }
    }
    float* dst = g_wc + (size_t)pe * (C * C);
    for (int idx = threadIdx.x; idx < C * C; idx += blockDim.x) {
        float s = 0.0f;
        for (int a = 0; a < cnt[0]; a++)
            for (int b = 0; b < cnt[1]; b++)
                for (int c = 0; c < cnt[2]; c++) {
                    int k = (offs[0][a] + 1) * 9 + (offs[1][b] + 1) * 3 + (offs[2][c] + 1);
                    s += W2[(size_t)k * (C * C) + idx];
                }
        dst[idx] = s;
    }
}

__device__ __forceinline__ void split_bf16(float x, __nv_bfloat16& hi, __nv_bfloat16& lo) {
    hi = __float2bfloat16(x);
    lo = __float2bfloat16(x - __bfloat162float(hi));
}

__global__ void split_feats_kernel(const float* __restrict__ f) {
    size_t i = (size_t)blockIdx.x * blockDim.x + threadIdx.x;
    const size_t tot = (size_t)(N_VOX + 1) * C;
    if (i >= tot) return;
    float x = (i < (size_t)N_VOX * C) ? f[i] : 0.0f;
    __nv_bfloat16 hi, lo; split_bf16(x, hi, lo);
    g_f_hi[i] = hi; g_f_lo[i] = lo;
    if (i >= (size_t)N_VOX * C) { g_h_hi[i] = __float2bfloat16(0.f); g_h_lo[i] = __float2bfloat16(0.f); }
}

__global__ void split_w1_kernel(const float* __restrict__ W1) {
    size_t i = (size_t)blockIdx.x * blockDim.x + threadIdx.x;
    if (i >= (size_t)27 * C * C) return;
    int k = i / (C * C); int r = i % (C * C); int ci = r / C; int co = r % C;
    __nv_bfloat16 hi, lo; split_bf16(W1[i], hi, lo);
    size_t o = (size_t)k * C * C + (size_t)co * C + ci;
    g_w1t_hi[o] = hi; g_w1t_lo[o] = lo;
}

__global__ void split_wc_kernel() {
    size_t i = (size_t)blockIdx.x * blockDim.x + threadIdx.x;
    if (i >= (size_t)64 * C * C) return;
    int pe = i / (C * C); int r = i % (C * C); int ci = r / C; int co = r % C;
    __nv_bfloat16 hi, lo; split_bf16(g_wc[i], hi, lo);
    size_t o = (size_t)pe * C * C + (size_t)co * C + ci;
    g_wct_hi[o] = hi; g_wct_lo[o] = lo;
}

// ---------------------------------------------------------------------------
// Main conv kernel: 256 threads, block = 128 voxels x 128 outputs.
// SMEM: [0,512) bias f32 | [512,14336) sIdx[NOFF][128] | [16384, +2*65536) buffers
//   buffer b: Ahi(16K) Alo(16K) Bhi(16K) Blo(16K); K chunk = 64 (2 chunks/tap).
// Swizzle: 16B chunk col c at row r stored at chunk (c ^ (r&7)).
// ---------------------------------------------------------------------------
#define BUF_OFF 16384
#define SMEM_TOTAL (16384 + 2 * 65536)

template <int NOFF, bool L2>
__global__ __launch_bounds__(256, 1)
void conv_mma(const __nv_bfloat16* __restrict__ fhi, const __nv_bfloat16* __restrict__ flo,
              const __nv_bfloat16* __restrict__ whi, const __nv_bfloat16* __restrict__ wlo,
              const int* __restrict__ nbr, const float* __restrict__ bias,
              float* __restrict__ out, __nv_bfloat16* __restrict__ ohi,
              __nv_bfloat16* __restrict__ olo) {
    extern __shared__ __align__(1024) char smem[];
    const uint32_t sb = smem_u32(smem);
    const int tx = threadIdx.x, wid = tx >> 5, lane = tx & 31;
    const int m0 = blockIdx.x * 128;
    const int p  = L2 ? blockIdx.y : 0;
    const int p0 = (p >> 2) & 1, p1 = (p >> 1) & 1, p2 = p & 1;
    const int wm = wid & 1;            // 0..1 : 64-row slab
    const int wn = wid >> 1;           // 0..3 : 32-col slab

    float* sBias = (float*)smem;
    int*   sIdx  = (int*)(smem + 512);

    // ---- preload bias + ALL tap gather indices ----
    if (tx < C) sBias[tx] = bias[tx];
    for (int t = tx; t < NOFF * 128; t += 256) {
        const int tap = t >> 7, r = t & 127;
        const int col = L2 ? ((((tap >> 2) & 1) + p0) * 9 + (((tap >> 1) & 1) + p1) * 3 + ((tap & 1) + p2))
                           : tap;
        const int row = m0 + r;
        sIdx[t] = (row < N_VOX) ? nbr[(size_t)row * 27 + col] : N_VOX;
    }
    __syncthreads();

    const int NCH = NOFF * 2;   // chunks (K=64 each)

    // chunk loader: gather A rows + stream B rows into buffer `buf`
    auto load_chunk = [&](int ch, int buf) {
        const int tap = ch >> 1;
        const int kb  = (ch & 1) * 64;                 // bf16 col base
        const uint32_t base = sb + BUF_OFF + (uint32_t)buf * 65536u;
        const int slice = L2 ? (p * 8 + tap) : tap;
        const __nv_bfloat16* wsl_h = whi + (size_t)slice * (C * C);
        const __nv_bfloat16* wsl_l = wlo + (size_t)slice * (C * C);
        const int* idx = sIdx + tap * 128;
        #pragma unroll
        for (int i = 0; i < 8; ++i) {                  // A: hi+lo, 2048 ops
            const int op = tx + i * 256;
            const int part = op >> 10;
            const int rc = op & 1023, row = rc >> 3, c = rc & 7;
            const int g = idx[row];
            const __nv_bfloat16* src = (part ? flo : fhi) + (size_t)g * C + kb + c * 8;
            const uint32_t dst = base + (uint32_t)part * 16384u
                               + (uint32_t)(row * 128 + ((c ^ (row & 7)) << 4));
            CP16(dst, src);
        }
        #pragma unroll
        for (int i = 0; i < 8; ++i) {                  // B: hi+lo
            const int op = tx + i * 256;
            const int part = op >> 10;
            const int rc = op & 1023, row = rc >> 3, c = rc & 7;
            const __nv_bfloat16* src = (part ? wsl_l : wsl_h) + (size_t)row * C + kb + c * 8;
            const uint32_t dst = base + 32768u + (uint32_t)part * 16384u
                               + (uint32_t)(row * 128 + ((c ^ (row & 7)) << 4));
            CP16(dst, src);
        }
    };

    float acc[4][4][4];
    #pragma unroll
    for (int i = 0; i < 4; i++)
        #pragma unroll
        for (int j = 0; j < 4; j++)
            #pragma unroll
            for (int q = 0; q < 4; q++) acc[i][j][q] = 0.0f;

    load_chunk(0, 0);
    CP_COMMIT();

    #pragma unroll 1
    for (int ch = 0; ch < NCH; ++ch) {
        if (ch + 1 < NCH) {
            load_chunk(ch + 1, (ch + 1) & 1);
            CP_COMMIT();
            CP_WAIT1();
        } else {
            CP_WAIT0();
        }
        __syncthreads();

        const uint32_t base = sb + BUF_OFF + (uint32_t)(ch & 1) * 65536u;
        const uint32_t aHi = base, aLo = base + 16384u, bHi = base + 32768u, bLo = base + 49152u;

        #pragma unroll
        for (int k16 = 0; k16 < 4; ++k16) {
            uint32_t ah[4][4], al[4][4], bh[4][2], bl[4][2];
            #pragma unroll
            for (int i = 0; i < 4; ++i) {
                const int row = wm * 64 + 16 * i + (lane & 15);
                const int c = (k16 << 1) + (lane >> 4);
                const uint32_t off = (uint32_t)(row * 128 + ((c ^ (row & 7)) << 4));
                ldsm_x4(ah[i], aHi + off);
                ldsm_x4(al[i], aLo + off);
            }
            #pragma unroll
            for (int jj = 0; jj < 2; ++jj) {
                const int grp = lane >> 3;
                const int row = wn * 32 + 16 * jj + ((grp >> 1) << 3) + (lane & 7);
                const int c = (k16 << 1) + (grp & 1);
                const uint32_t off = (uint32_t)(row * 128 + ((c ^ (row & 7)) << 4));
                uint32_t t[4];
                ldsm_x4(t, bHi + off);
                bh[jj * 2][0] = t[0]; bh[jj * 2][1] = t[1];
                bh[jj * 2 + 1][0] = t[2]; bh[jj * 2 + 1][1] = t[3];
                ldsm_x4(t, bLo + off);
                bl[jj * 2][0] = t[0]; bl[jj * 2][1] = t[1];
                bl[jj * 2 + 1][0] = t[2]; bl[jj * 2 + 1][1] = t[3];
            }
            #pragma unroll
            for (int i = 0; i < 4; ++i)
                #pragma unroll
                for (int j = 0; j < 4; ++j) {
                    mma16816(acc[i][j], ah[i], bh[j]);
                    mma16816(acc[i][j], ah[i], bl[j]);
                    mma16816(acc[i][j], al[i], bh[j]);
                }
        }
        __syncthreads();
    }

    // ---- epilogue: bias + SiLU ----
    const int lrow = lane >> 2;             // 0..7
    const int lcol = (lane & 3) * 2;        // 0,2,4,6
    #pragma unroll
    for (int i = 0; i < 4; ++i) {
        const int r0 = m0 + wm * 64 + 16 * i + lrow;
        const int r1 = r0 + 8;
        #pragma unroll
        for (int j = 0; j < 4; ++j) {
            const int cb = wn * 32 + 8 * j + lcol;
            const float b0 = sBias[cb], b1 = sBias[cb + 1];
            float v00 = silu_f(acc[i][j][0] + b0), v01 = silu_f(acc[i][j][1] + b1);
            float v10 = silu_f(acc[i][j][2] + b0), v11 = silu_f(acc[i][j][3] + b1);
            if (L2) {
                if (r0 < N_VOX) *(float2*)(out + ((size_t)r0 * 8 + p) * C + cb) = make_float2(v00, v01);
                if (r1 < N_VOX) *(float2*)(out + ((size_t)r1 * 8 + p) * C + cb) = make_float2(v10, v11);
            } else {
                __nv_bfloat16 h0, l0, h1, l1;
                if (r0 < N_VOX) {
                    split_bf16(v00, h0, l0); split_bf16(v01, h1, l1);
                    *(__nv_bfloat162*)(ohi + (size_t)r0 * C + cb) = __nv_bfloat162(h0, h1);
                    *(__nv_bfloat162*)(olo + (size_t)r0 * C + cb) = __nv_bfloat162(l0, l1);
                }
                if (r1 < N_VOX) {
                    split_bf16(v10, h0, l0); split_bf16(v11, h1, l1);
                    *(__nv_bfloat162*)(ohi + (size_t)r1 * C + cb) = __nv_bfloat162(h0, h1);
                    *(__nv_bfloat162*)(olo + (size_t)r1 * C + cb) = __nv_bfloat162(l0, l1);
                }
            }
        }
    }
}

// ---------------------------------------------------------------------------
// Inputs (metadata order): feats, W1, b1, W2, b2, nbr1, nbr2(unused)
// Output: 320000 x 128 fp32
// ---------------------------------------------------------------------------
extern "C" void kernel_launch(void* const* d_in, const int* in_sizes, int n_in,
                              void* d_out, int out_size) {
    const float* feats = (const float*)d_in[0];
    const float* W1    = (const float*)d_in[1];
    const float* b1    = (const float*)d_in[2];
    const float* W2    = (const float*)d_in[3];
    const float* b2    = (const float*)d_in[4];
    const int*   nbr1  = (const int*)  d_in[5];
    float*       out   = (float*)d_out;

    __nv_bfloat16 *fhi, *flo, *hhi, *hlo, *w1h, *w1l, *wch, *wcl;
    cudaGetSymbolAddress((void**)&fhi, g_f_hi);
    cudaGetSymbolAddress((void**)&flo, g_f_lo);
    cudaGetSymbolAddress((void**)&hhi, g_h_hi);
    cudaGetSymbolAddress((void**)&hlo, g_h_lo);
    cudaGetSymbolAddress((void**)&w1h, g_w1t_hi);
    cudaGetSymbolAddress((void**)&w1l, g_w1t_lo);
    cudaGetSymbolAddress((void**)&wch, g_wct_hi);
    cudaGetSymbolAddress((void**)&wcl, g_wct_lo);

    cudaFuncSetAttribute(conv_mma<27, false>, cudaFuncAttributeMaxDynamicSharedMemorySize, SMEM_TOTAL);
    cudaFuncSetAttribute(conv_mma<8,  true >, cudaFuncAttributeMaxDynamicSharedMemorySize, SMEM_TOTAL);

    // prep
    build_wc_kernel<<<64, 256>>>(W2);
    split_wc_kernel<<<(64 * C * C + 255) / 256, 256>>>();
    split_w1_kernel<<<(27 * C * C + 255) / 256, 256>>>(W1);
    split_feats_kernel<<<((N_VOX + 1) * C + 255) / 256, 256>>>(feats);

    // layer 1: 27-tap conv -> h (bf16 hi/lo)
    conv_mma<27, false><<<NBLK, 256, SMEM_TOTAL>>>(fhi, flo, w1h, w1l, nbr1, b1,
                                                   nullptr, hhi, hlo);
    // layer 2 (collapsed subdivide): 8-tap conv on coarse grid -> out fp32
    conv_mma<8, true><<<dim3(NBLK, 8), 256, SMEM_TOTAL>>>(hhi, hlo, wch, wcl, nbr1, b2,
                                                          out, nullptr, nullptr);
}

// round 7
// speedup vs baseline: 2.5544x; 1.1667x over previous
#include <cuda_runtime.h>
#include <cuda_bf16.h>
#include <cstdint>

// ============================================================================
// SparseSubdivideBlock3d via legacy HMMA (mma.sync bf16) + bf16x3 fp32 emulation.
// R7: 64x128 block tile, 2 CTAs/SM (16 warps), one sync per K-chunk.
//
// Algorithm (validated R4 @ fp32, R6 @ bf16x3):
//   conv1: 27-tap submanifold conv, C=128->128, +bias, SiLU
//   subdivide collapse: conv2 == 8-tap conv on the COARSE grid with
//     pre-combined weights Wc[p][e] = sum W2[k], out row = 8*v + p.
// Numerics: x = hi + lo (bf16 each); A.B ~= Ahi.Bhi + Ahi.Blo + Alo.Bhi.
// ============================================================================

#define N_VOX 40000
#define C 128

// ---- device scratch ----
__device__ __align__(16) __nv_bfloat16 g_w1t_hi[27 * C * C];      // W1^T [k][co][ci]
__device__ __align__(16) __nv_bfloat16 g_w1t_lo[27 * C * C];
__device__ __align__(16) __nv_bfloat16 g_wct_hi[64 * C * C];      // Wc^T [pe][co][ci]
__device__ __align__(16) __nv_bfloat16 g_wct_lo[64 * C * C];
__device__ __align__(16) __nv_bfloat16 g_f_hi[(N_VOX + 1) * C];   // feats split + zero pad row
__device__ __align__(16) __nv_bfloat16 g_f_lo[(N_VOX + 1) * C];
__device__ __align__(16) __nv_bfloat16 g_h_hi[(N_VOX + 1) * C];   // layer-1 out split + pad
__device__ __align__(16) __nv_bfloat16 g_h_lo[(N_VOX + 1) * C];

__device__ __forceinline__ float silu_f(float x) { return x / (1.0f + __expf(-x)); }

__device__ __forceinline__ uint32_t smem_u32(const void* p) {
    uint32_t a;
    asm("{ .reg .u64 t; cvta.to.shared.u64 t, %1; cvt.u32.u64 %0, t; }" : "=r"(a) : "l"(p));
    return a;
}
#define CP16(dst, src) asm volatile("cp.async.cg.shared.global [%0], [%1], 16;" :: "r"(dst), "l"(src))
#define CP_COMMIT()    asm volatile("cp.async.commit_group;" ::: "memory")
#define CP_WAIT1()     asm volatile("cp.async.wait_group 1;" ::: "memory")

__device__ __forceinline__ void ldsm_x4(uint32_t* r, uint32_t a) {
    asm volatile("ldmatrix.sync.aligned.m8n8.x4.shared.b16 {%0,%1,%2,%3}, [%4];"
                 : "=r"(r[0]), "=r"(r[1]), "=r"(r[2]), "=r"(r[3]) : "r"(a));
}
__device__ __forceinline__ void mma16816(float* d, const uint32_t* a, const uint32_t* b) {
    asm volatile("mma.sync.aligned.m16n8k16.row.col.f32.bf16.bf16.f32 "
                 "{%0,%1,%2,%3}, {%4,%5,%6,%7}, {%8,%9}, {%0,%1,%2,%3};"
                 : "+f"(d[0]), "+f"(d[1]), "+f"(d[2]), "+f"(d[3])
                 : "r"(a[0]), "r"(a[1]), "r"(a[2]), "r"(a[3]), "r"(b[0]), "r"(b[1]));
}

__device__ __forceinline__ void split_bf16(float x, __nv_bfloat16& hi, __nv_bfloat16& lo) {
    hi = __float2bfloat16(x);
    lo = __float2bfloat16(x - __bfloat162float(hi));
}

// ---------------------------------------------------------------------------
// Prep: fused build + split + transpose for Wc (and W1), SMEM tile transpose.
// Wc[p][e][ci][co] = sum of W2[k] over fine offsets mapping to parent offset
// d = e + p - 1 per dim; output transposed/split: g_wct_{hi,lo}[pe][co][ci].
// grid (16 tiles, 64 pe), 256 threads; tile = 32x32 of (ci, co).
// ---------------------------------------------------------------------------
__global__ void build_wct_kernel(const float* __restrict__ W2) {
    __shared__ float s[32][33];
    const int pe = blockIdx.y;
    const int p = pe >> 3, e = pe & 7;
    const int pp[3] = { (p >> 2) & 1, (p >> 1) & 1, p & 1 };
    const int ee[3] = { (e >> 2) & 1, (e >> 1) & 1, e & 1 };
    int offs[3][2], cnt[3];
    #pragma unroll
    for (int d = 0; d < 3; d++) {
        if (ee[d] == pp[d]) { cnt[d] = 1; offs[d][0] = pp[d] ? 1 : -1; offs[d][1] = 0; }
        else if (pp[d] == 0) { cnt[d] = 2; offs[d][0] = 0;  offs[d][1] = 1; }
        else                 { cnt[d] = 2; offs[d][0] = -1; offs[d][1] = 0; }
    }
    const int ci0 = (blockIdx.x >> 2) * 32, co0 = (blockIdx.x & 3) * 32;
    const int tx = threadIdx.x;
    const int r = tx >> 3, c4 = (tx & 7) * 4;

    float4 sum = make_float4(0.f, 0.f, 0.f, 0.f);
    for (int a = 0; a < cnt[0]; a++)
        for (int b = 0; b < cnt[1]; b++)
            for (int c = 0; c < cnt[2]; c++) {
                int k = (offs[0][a] + 1) * 9 + (offs[1][b] + 1) * 3 + (offs[2][c] + 1);
                float4 v = *(const float4*)(W2 + (size_t)k * (C * C) + (size_t)(ci0 + r) * C + co0 + c4);
                sum.x += v.x; sum.y += v.y; sum.z += v.z; sum.w += v.w;
            }
    s[r][c4] = sum.x; s[r][c4 + 1] = sum.y; s[r][c4 + 2] = sum.z; s[r][c4 + 3] = sum.w;
    __syncthreads();

    // transposed write: thread -> (co = r, ci4 = c4)
    __nv_bfloat16 hi[4], lo[4];
    #pragma unroll
    for (int j = 0; j < 4; ++j) split_bf16(s[c4 + j][r], hi[j], lo[j]);
    const size_t o = (size_t)pe * (C * C) + (size_t)(co0 + r) * C + ci0 + c4;
    *(uint2*)(g_wct_hi + o) = *(const uint2*)hi;
    *(uint2*)(g_wct_lo + o) = *(const uint2*)lo;
}

// same for W1: grid (16 tiles, 27 taps)
__global__ void build_w1t_kernel(const float* __restrict__ W1) {
    __shared__ float s[32][33];
    const int k = blockIdx.y;
    const int ci0 = (blockIdx.x >> 2) * 32, co0 = (blockIdx.x & 3) * 32;
    const int tx = threadIdx.x;
    const int r = tx >> 3, c4 = (tx & 7) * 4;
    float4 v = *(const float4*)(W1 + (size_t)k * (C * C) + (size_t)(ci0 + r) * C + co0 + c4);
    s[r][c4] = v.x; s[r][c4 + 1] = v.y; s[r][c4 + 2] = v.z; s[r][c4 + 3] = v.w;
    __syncthreads();
    __nv_bfloat16 hi[4], lo[4];
    #pragma unroll
    for (int j = 0; j < 4; ++j) split_bf16(s[c4 + j][r], hi[j], lo[j]);
    const size_t o = (size_t)k * (C * C) + (size_t)(co0 + r) * C + ci0 + c4;
    *(uint2*)(g_w1t_hi + o) = *(const uint2*)hi;
    *(uint2*)(g_w1t_lo + o) = *(const uint2*)lo;
}

// feats split (vectorized), also zeroes pad rows of f and h
__global__ void split_feats_kernel(const float* __restrict__ f) {
    const size_t i4 = ((size_t)blockIdx.x * blockDim.x + threadIdx.x) * 4;
    const size_t tot = (size_t)(N_VOX + 1) * C;
    if (i4 >= tot) return;
    float4 v;
    const bool pad = i4 >= (size_t)N_VOX * C;
    if (pad) v = make_float4(0.f, 0.f, 0.f, 0.f);
    else     v = *(const float4*)(f + i4);
    __nv_bfloat16 hi[4], lo[4];
    split_bf16(v.x, hi[0], lo[0]); split_bf16(v.y, hi[1], lo[1]);
    split_bf16(v.z, hi[2], lo[2]); split_bf16(v.w, hi[3], lo[3]);
    *(uint2*)(g_f_hi + i4) = *(const uint2*)hi;
    *(uint2*)(g_f_lo + i4) = *(const uint2*)lo;
    if (pad) {
        *(uint2*)(g_h_hi + i4) = *(const uint2*)hi;   // zeros
        *(uint2*)(g_h_lo + i4) = *(const uint2*)lo;
    }
}

// ---------------------------------------------------------------------------
// Main conv kernel: 256 threads, block = 64 voxels x 128 outputs, 2 CTAs/SM.
// SMEM: [0,512) bias | [512, 512+NOFF*256) sIdx | [8192, +2*49152) stage bufs
//   stage: Ahi 8K | Alo 8K | Bhi 16K | Blo 16K  (K chunk = 64)
// Swizzle: 16B chunk col c at row r stored at chunk (c ^ (r&7)); row = 128B.
// ---------------------------------------------------------------------------
#define BUF_OFF 8192
#define STAGE   49152
#define SMEM_TOTAL (BUF_OFF + 2 * STAGE)

template <int NOFF, bool L2>
__global__ __launch_bounds__(256, 2)
void conv_mma(const __nv_bfloat16* __restrict__ fhi, const __nv_bfloat16* __restrict__ flo,
              const __nv_bfloat16* __restrict__ whi, const __nv_bfloat16* __restrict__ wlo,
              const int* __restrict__ nbr, const float* __restrict__ bias,
              float* __restrict__ out, __nv_bfloat16* __restrict__ ohi,
              __nv_bfloat16* __restrict__ olo) {
    extern __shared__ __align__(1024) char smem[];
    const uint32_t sb = smem_u32(smem);
    const int tx = threadIdx.x, wid = tx >> 5, lane = tx & 31;
    const int m0 = blockIdx.x * 64;
    const int p  = L2 ? blockIdx.y : 0;
    const int p0 = (p >> 2) & 1, p1 = (p >> 1) & 1, p2 = p & 1;
    const int wm = wid & 1;            // 0..1 : 32-row slab
    const int wn = wid >> 1;           // 0..3 : 32-col slab

    float* sBias = (float*)smem;
    int*   sIdx  = (int*)(smem + 512);

    if (tx < C) sBias[tx] = bias[tx];
    for (int t = tx; t < NOFF * 64; t += 256) {
        const int tap = t >> 6, r = t & 63;
        const int col = L2 ? ((((tap >> 2) & 1) + p0) * 9 + (((tap >> 1) & 1) + p1) * 3 + ((tap & 1) + p2))
                           : tap;
        sIdx[t] = nbr[(size_t)(m0 + r) * 27 + col];   // 625*64 == N_VOX exactly
    }
    __syncthreads();

    const int NCH = NOFF;   // one K=128?  no: chunk = one tap half? -> K=64 chunks, 2 per tap
    const int NCHUNK = NOFF * 2;

    auto load_chunk = [&](int ch, int buf) {
        const int tap = ch >> 1;
        const int kb  = (ch & 1) * 64;
        const uint32_t base = sb + BUF_OFF + (uint32_t)buf * STAGE;
        const int slice = L2 ? (p * 8 + tap) : tap;
        const __nv_bfloat16* wsl_h = whi + (size_t)slice * (C * C);
        const __nv_bfloat16* wsl_l = wlo + (size_t)slice * (C * C);
        const int* idx = sIdx + tap * 64;
        #pragma unroll
        for (int i = 0; i < 4; ++i) {                  // A hi+lo: 1024 chunks
            const int op = tx + i * 256;
            const int part = op >> 9;
            const int rc = op & 511, row = rc >> 3, c = rc & 7;
            const int g = idx[row];
            const __nv_bfloat16* src = (part ? flo : fhi) + (size_t)g * C + kb + c * 8;
            const uint32_t dst = base + (uint32_t)part * 8192u
                               + (uint32_t)(row * 128 + ((c ^ (row & 7)) << 4));
            CP16(dst, src);
        }
        #pragma unroll
        for (int i = 0; i < 8; ++i) {                  // B hi+lo: 2048 chunks
            const int op = tx + i * 256;
            const int part = op >> 10;
            const int rc = op & 1023, row = rc >> 3, c = rc & 7;
            const __nv_bfloat16* src = (part ? wsl_l : wsl_h) + (size_t)row * C + kb + c * 8;
            const uint32_t dst = base + 16384u + (uint32_t)part * 16384u
                               + (uint32_t)(row * 128 + ((c ^ (row & 7)) << 4));
            CP16(dst, src);
        }
    };

    float acc[2][4][4];
    #pragma unroll
    for (int i = 0; i < 2; i++)
        #pragma unroll
        for (int j = 0; j < 4; j++)
            #pragma unroll
            for (int q = 0; q < 4; q++) acc[i][j][q] = 0.0f;

    load_chunk(0, 0);
    CP_COMMIT();

    #pragma unroll 1
    for (int ch = 0; ch < NCHUNK; ++ch) {
        __syncthreads();                       // buffer (ch+1)&1 free for reuse
        if (ch + 1 < NCHUNK) load_chunk(ch + 1, (ch + 1) & 1);
        CP_COMMIT();                           // may be an empty group at tail
        CP_WAIT1();                            // group for chunk `ch` complete
        __syncthreads();

        const uint32_t base = sb + BUF_OFF + (uint32_t)(ch & 1) * STAGE;
        const uint32_t aHi = base, aLo = base + 8192u, bHi = base + 16384u, bLo = base + 32768u;

        #pragma unroll
        for (int k16 = 0; k16 < 4; ++k16) {
            uint32_t ah[2][4], al[2][4], bh[4][2], bl[4][2];
            #pragma unroll
            for (int i = 0; i < 2; ++i) {
                const int row = wm * 32 + 16 * i + (lane & 15);
                const int c = (k16 << 1) + (lane >> 4);
                const uint32_t off = (uint32_t)(row * 128 + ((c ^ (row & 7)) << 4));
                ldsm_x4(ah[i], aHi + off);
                ldsm_x4(al[i], aLo + off);
            }
            #pragma unroll
            for (int jj = 0; jj < 2; ++jj) {
                const int grp = lane >> 3;
                const int row = wn * 32 + 16 * jj + ((grp >> 1) << 3) + (lane & 7);
                const int c = (k16 << 1) + (grp & 1);
                const uint32_t off = (uint32_t)(row * 128 + ((c ^ (row & 7)) << 4));
                uint32_t t[4];
                ldsm_x4(t, bHi + off);
                bh[jj * 2][0] = t[0]; bh[jj * 2][1] = t[1];
                bh[jj * 2 + 1][0] = t[2]; bh[jj * 2 + 1][1] = t[3];
                ldsm_x4(t, bLo + off);
                bl[jj * 2][0] = t[0]; bl[jj * 2][1] = t[1];
                bl[jj * 2 + 1][0] = t[2]; bl[jj * 2 + 1][1] = t[3];
            }
            #pragma unroll
            for (int i = 0; i < 2; ++i)
                #pragma unroll
                for (int j = 0; j < 4; ++j) {
                    mma16816(acc[i][j], ah[i], bh[j]);
                    mma16816(acc[i][j], ah[i], bl[j]);
                    mma16816(acc[i][j], al[i], bh[j]);
                }
        }
    }
    (void)NCH;

    // ---- epilogue: bias + SiLU ----
    const int lrow = lane >> 2;             // 0..7
    const int lcol = (lane & 3) * 2;        // 0,2,4,6
    #pragma unroll
    for (int i = 0; i < 2; ++i) {
        const int r0 = m0 + wm * 32 + 16 * i + lrow;
        const int r1 = r0 + 8;
        #pragma unroll
        for (int j = 0; j < 4; ++j) {
            const int cb = wn * 32 + 8 * j + lcol;
            const float b0 = sBias[cb], b1 = sBias[cb + 1];
            float v00 = silu_f(acc[i][j][0] + b0), v01 = silu_f(acc[i][j][1] + b1);
            float v10 = silu_f(acc[i][j][2] + b0), v11 = silu_f(acc[i][j][3] + b1);
            if (L2) {
                *(float2*)(out + ((size_t)r0 * 8 + p) * C + cb) = make_float2(v00, v01);
                *(float2*)(out + ((size_t)r1 * 8 + p) * C + cb) = make_float2(v10, v11);
            } else {
                __nv_bfloat16 h0, l0, h1, l1;
                split_bf16(v00, h0, l0); split_bf16(v01, h1, l1);
                *(__nv_bfloat162*)(ohi + (size_t)r0 * C + cb) = __nv_bfloat162(h0, h1);
                *(__nv_bfloat162*)(olo + (size_t)r0 * C + cb) = __nv_bfloat162(l0, l1);
                split_bf16(v10, h0, l0); split_bf16(v11, h1, l1);
                *(__nv_bfloat162*)(ohi + (size_t)r1 * C + cb) = __nv_bfloat162(h0, h1);
                *(__nv_bfloat162*)(olo + (size_t)r1 * C + cb) = __nv_bfloat162(l0, l1);
            }
        }
    }
}

// ---------------------------------------------------------------------------
// Inputs (metadata order): feats, W1, b1, W2, b2, nbr1, nbr2(unused)
// Output: 320000 x 128 fp32
// ---------------------------------------------------------------------------
extern "C" void kernel_launch(void* const* d_in, const int* in_sizes, int n_in,
                              void* d_out, int out_size) {
    const float* feats = (const float*)d_in[0];
    const float* W1    = (const float*)d_in[1];
    const float* b1    = (const float*)d_in[2];
    const float* W2    = (const float*)d_in[3];
    const float* b2    = (const float*)d_in[4];
    const int*   nbr1  = (const int*)  d_in[5];
    float*       out   = (float*)d_out;

    __nv_bfloat16 *fhi, *flo, *hhi, *hlo, *w1h, *w1l, *wch, *wcl;
    cudaGetSymbolAddress((void**)&fhi, g_f_hi);
    cudaGetSymbolAddress((void**)&flo, g_f_lo);
    cudaGetSymbolAddress((void**)&hhi, g_h_hi);
    cudaGetSymbolAddress((void**)&hlo, g_h_lo);
    cudaGetSymbolAddress((void**)&w1h, g_w1t_hi);
    cudaGetSymbolAddress((void**)&w1l, g_w1t_lo);
    cudaGetSymbolAddress((void**)&wch, g_wct_hi);
    cudaGetSymbolAddress((void**)&wcl, g_wct_lo);

    cudaFuncSetAttribute(conv_mma<27, false>, cudaFuncAttributeMaxDynamicSharedMemorySize, SMEM_TOTAL);
    cudaFuncSetAttribute(conv_mma<8,  true >, cudaFuncAttributeMaxDynamicSharedMemorySize, SMEM_TOTAL);

    // prep
    build_wct_kernel<<<dim3(16, 64), 256>>>(W2);
    build_w1t_kernel<<<dim3(16, 27), 256>>>(W1);
    split_feats_kernel<<<((N_VOX + 1) * C / 4 + 255) / 256, 256>>>(feats);

    const int nblk = N_VOX / 64;   // 625
    // layer 1: 27-tap conv -> h (bf16 hi/lo)
    conv_mma<27, false><<<nblk, 256, SMEM_TOTAL>>>(fhi, flo, w1h, w1l, nbr1, b1,
                                                   nullptr, hhi, hlo);
    // layer 2 (collapsed subdivide): 8-tap conv on coarse grid -> out fp32
    conv_mma<8, true><<<dim3(nblk, 8), 256, SMEM_TOTAL>>>(hhi, hlo, wch, wcl, nbr1, b2,
                                                          out, nullptr, nullptr);
}